// round 1
// baseline (speedup 1.0000x reference)
#include <cuda_runtime.h>

#define NB 16
#define TQ 256
#define TK 256
#define DD 256
#define FF 36
#define HH 8
#define DK 32
#define SFD 6

// Scratch (allocation-free rule: __device__ globals)
__device__ float g_Q[NB*TQ*DD];        // [b][q][h*DK+j]
__device__ float g_K[NB*TK*DD];        // [b][k][h*DK+j]
__device__ float g_E[NB*HH*TQ*TK];     // [b][h][q][k] = exp(score)
__device__ float g_HN[NB*TQ*FF*HH];    // [b][q][f][h] = softmax-weighted value

// ---------------------------------------------------------------------------
// Kernel 1: head projections. One block per row n = b*T + t; thread = h*32+j.
// out[n, h*DK+j] = sum_d x[n,d] * W[h,d,j]
// ---------------------------------------------------------------------------
__global__ void proj_kernel(const float* __restrict__ x,
                            const float* __restrict__ W,
                            int which) {
    __shared__ float xs[DD];
    int n = blockIdx.x;
    int t = threadIdx.x;
    xs[t] = x[n*DD + t];
    __syncthreads();
    int h = t >> 5, j = t & 31;
    const float* w = W + h*DD*DK + j;   // stride DK over d
    float acc = 0.f;
#pragma unroll 16
    for (int d = 0; d < DD; ++d) acc = fmaf(xs[d], w[d*DK], acc);
    float* out = which ? g_K : g_Q;
    out[n*DD + t] = acc;
}

// ---------------------------------------------------------------------------
// Kernel 2: E[b,h,q,k] = exp(Q[b,h,q,:] . K[b,h,k,:])   (no max-subtraction;
// logits bounded ~|25| so fp32 exp/sum is safe).
// Block = (b, h, qtile of 64). Thread t owns k=t, loops q. Writes coalesced.
// ---------------------------------------------------------------------------
__global__ void score_kernel() {
    int b = blockIdx.x, h = blockIdx.y;
    int qb = blockIdx.z * 64;
    int t = threadIdx.x;                 // k index
    __shared__ float Qs[64][32];         // broadcast reads -> no conflicts
    __shared__ float Ks[256][33];        // padded: thread t reads row t

    // cooperative, coalesced loads
    for (int i = t; i < 64*32; i += 256) {
        int q = i >> 5, j = i & 31;
        Qs[q][j] = g_Q[(b*TQ + qb + q)*DD + h*DK + j];
    }
    for (int i = t; i < 256*32; i += 256) {
        int k = i >> 5, j = i & 31;
        Ks[k][j] = g_K[(b*TK + k)*DD + h*DK + j];
    }
    __syncthreads();

    float kr[32];
#pragma unroll
    for (int j = 0; j < 32; ++j) kr[j] = Ks[t][j];

    float* ep = g_E + ((size_t)(b*HH + h)*TQ + qb)*TK + t;
#pragma unroll 4
    for (int q = 0; q < 64; ++q) {
        float s = 0.f;
#pragma unroll
        for (int j = 0; j < 32; ++j) s = fmaf(kr[j], Qs[q][j], s);
        ep[(size_t)q*TK] = __expf(fminf(s, 80.f));
    }
}

// ---------------------------------------------------------------------------
// Kernel 3: num/den = E[b,h] (256x256) @ [mask*value | mask] (256x36 each).
// Block = (b,h), 256 threads: thread (qg=t>>2 -> 4 q rows, fg=t&3 -> 9 f cols),
// 72 fp32 accumulators. k tiled by 32 through SMEM.
// Writes g_HN[b][q][f][h] = num/den.
// ---------------------------------------------------------------------------
__global__ void apply_kernel(const float* __restrict__ value,
                             const float* __restrict__ mask) {
    int b = blockIdx.x, h = blockIdx.y;
    int t = threadIdx.x;
    int qg = t >> 2;       // q = qg*4 + qq
    int fg = t & 3;        // f = fg*9 + i

    __shared__ float Es[TQ][33];     // [q][kk], padded (bank = q+kk)
    __shared__ float mvs[32][FF];
    __shared__ float ms[32][FF];

    float num[4][9], den[4][9];
#pragma unroll
    for (int qq = 0; qq < 4; ++qq)
#pragma unroll
        for (int i = 0; i < 9; ++i) { num[qq][i] = 0.f; den[qq][i] = 0.f; }

    const float* Ebase = g_E + (size_t)(b*HH + h)*TQ*TK;

    for (int kt = 0; kt < TK; kt += 32) {
        __syncthreads();
        for (int i = t; i < TQ*32; i += 256) {
            int q = i >> 5, kk = i & 31;
            Es[q][kk] = Ebase[(size_t)q*TK + kt + kk];
        }
        for (int i = t; i < 32*FF; i += 256) {
            int kk = i / FF, f = i % FF;
            float mm = mask [(b*TK + kt + kk)*FF + f];
            float vv = value[(b*TK + kt + kk)*FF + f];
            ms[kk][f]  = mm;
            mvs[kk][f] = mm * vv;
        }
        __syncthreads();

        for (int kk = 0; kk < 32; ++kk) {
            float mv9[9], m9[9];
#pragma unroll
            for (int i = 0; i < 9; ++i) { mv9[i] = mvs[kk][fg*9+i]; m9[i] = ms[kk][fg*9+i]; }
#pragma unroll
            for (int qq = 0; qq < 4; ++qq) {
                float e = Es[qg*4 + qq][kk];
#pragma unroll
                for (int i = 0; i < 9; ++i) {
                    num[qq][i] = fmaf(e, mv9[i], num[qq][i]);
                    den[qq][i] = fmaf(e, m9[i],  den[qq][i]);
                }
            }
        }
    }

#pragma unroll
    for (int qq = 0; qq < 4; ++qq) {
        int q = qg*4 + qq;
        float* o = g_HN + ((size_t)(b*TQ + q)*FF)*HH + h;
#pragma unroll
        for (int i = 0; i < 9; ++i) {
            int f = fg*9 + i;
            o[f*HH] = num[qq][i] / den[qq][i];
        }
    }
}

// ---------------------------------------------------------------------------
// Kernel 4: fused epilogue. Block per (b,q), thread per d.
// lat[f] = tanh(sum_h hn[f,h]*Wc[h,d] + bc[d])
// out[d] = sum_s tanh(sum_f lat[f]*Wo1[f,s] + bo1[s]) * Wo2[s] + bo2[d]
// ---------------------------------------------------------------------------
__device__ __forceinline__ float tanh_fast(float x) {
    x = fminf(fmaxf(x, -15.f), 15.f);
    float e = __expf(2.f * x);
    return (e - 1.f) / (e + 1.f);
}

__global__ void epilogue_kernel(const float* __restrict__ Wc,
                                const float* __restrict__ bc,
                                const float* __restrict__ Wo1,
                                const float* __restrict__ bo1,
                                const float* __restrict__ Wo2,
                                const float* __restrict__ bo2,
                                float* __restrict__ out) {
    int bq = blockIdx.x;
    int d = threadIdx.x;
    __shared__ float hs[FF*HH];     // 288
    __shared__ float w1[FF*SFD];    // 216
    __shared__ float b1s[SFD], w2[SFD];

    for (int i = d; i < FF*HH; i += 256) hs[i] = g_HN[(size_t)bq*FF*HH + i];
    if (d < FF*SFD) w1[d] = Wo1[d];
    if (d < SFD) { b1s[d] = bo1[d]; w2[d] = Wo2[d]; }
    __syncthreads();

    float wc[HH];
#pragma unroll
    for (int h = 0; h < HH; ++h) wc[h] = Wc[h*DD + d];

    float lat[FF];
    float bcd = bc[d];
#pragma unroll
    for (int f = 0; f < FF; ++f) {
        float a = bcd;
#pragma unroll
        for (int h = 0; h < HH; ++h) a = fmaf(hs[f*HH + h], wc[h], a);
        lat[f] = tanh_fast(a);
    }

    float acc = bo2[d];
#pragma unroll
    for (int s = 0; s < SFD; ++s) {
        float a = b1s[s];
#pragma unroll
        for (int f = 0; f < FF; ++f) a = fmaf(lat[f], w1[f*SFD + s], a);
        acc = fmaf(tanh_fast(a), w2[s], acc);
    }
    out[(size_t)bq*DD + d] = acc;
}

// ---------------------------------------------------------------------------
extern "C" void kernel_launch(void* const* d_in, const int* in_sizes, int n_in,
                              void* d_out, int out_size) {
    const float* query = (const float*)d_in[0];
    const float* key   = (const float*)d_in[1];
    const float* value = (const float*)d_in[2];
    const float* mask  = (const float*)d_in[3];
    const float* Wq    = (const float*)d_in[4];
    const float* Wk    = (const float*)d_in[5];
    const float* Wc    = (const float*)d_in[6];
    const float* bc    = (const float*)d_in[7];
    const float* Wo1   = (const float*)d_in[8];
    const float* bo1   = (const float*)d_in[9];
    const float* Wo2   = (const float*)d_in[10];
    const float* bo2   = (const float*)d_in[11];
    float* out = (float*)d_out;

    proj_kernel<<<NB*TQ, 256>>>(query, Wq, 0);
    proj_kernel<<<NB*TK, 256>>>(key,   Wk, 1);
    score_kernel<<<dim3(NB, HH, 4), 256>>>();
    apply_kernel<<<dim3(NB, HH), 256>>>(value, mask);
    epilogue_kernel<<<NB*TQ, 256>>>(Wc, bc, Wo1, bo1, Wo2, bo2, out);
}

// round 2
// speedup vs baseline: 1.3612x; 1.3612x over previous
#include <cuda_runtime.h>

#define NB 16
#define TQ 256
#define TK 256
#define DD 256
#define FF 36
#define HH 8
#define DK 32
#define SFD 6

// Scratch (allocation-free rule: __device__ globals)
__device__ float g_Q[NB*TQ*DD];        // [b][q][h*DK+j]
__device__ float g_K[NB*TK*DD];        // [b][k][h*DK+j]
__device__ float g_E[NB*HH*TQ*TK];     // [b][h][q][k] = exp(score)
__device__ float g_HN[NB*TQ*FF*HH];    // [b][q][f][h] = softmax-weighted value

// ---------------------------------------------------------------------------
// Kernel 1: head projections, 16 rows per block (W reuse x16 -> L2 traffic /16).
// grid (NB*TQ/16, 2): y=0 -> query->g_Q, y=1 -> key->g_K.
// Thread t = h*32+j. acc[16] rows in registers; per d: 1 LDG(w) +
// 4 broadcast LDS.128 (x of 16 rows) + 16 FMA.
// ---------------------------------------------------------------------------
__global__ void proj_kernel(const float* __restrict__ query,
                            const float* __restrict__ key,
                            const float* __restrict__ Wq,
                            const float* __restrict__ Wk) {
    __shared__ float xst[DD][20];        // transposed, pad 20 -> 16B-aligned rows
    int n0 = blockIdx.x * 16;
    int which = blockIdx.y;
    const float* x = which ? key : query;
    const float* W = which ? Wk : Wq;
    int t = threadIdx.x;

#pragma unroll
    for (int r = 0; r < 16; ++r)
        xst[t][r] = x[(size_t)(n0 + r)*DD + t];
    __syncthreads();

    int h = t >> 5, j = t & 31;
    const float* w = W + h*DD*DK + j;    // stride DK over d

    float acc[16];
#pragma unroll
    for (int r = 0; r < 16; ++r) acc[r] = 0.f;

#pragma unroll 8
    for (int d = 0; d < DD; ++d) {
        float wv = w[d*DK];
        const float4* xr = (const float4*)&xst[d][0];
        float4 a = xr[0], b = xr[1], c = xr[2], e = xr[3];
        acc[0]  = fmaf(wv, a.x, acc[0]);  acc[1]  = fmaf(wv, a.y, acc[1]);
        acc[2]  = fmaf(wv, a.z, acc[2]);  acc[3]  = fmaf(wv, a.w, acc[3]);
        acc[4]  = fmaf(wv, b.x, acc[4]);  acc[5]  = fmaf(wv, b.y, acc[5]);
        acc[6]  = fmaf(wv, b.z, acc[6]);  acc[7]  = fmaf(wv, b.w, acc[7]);
        acc[8]  = fmaf(wv, c.x, acc[8]);  acc[9]  = fmaf(wv, c.y, acc[9]);
        acc[10] = fmaf(wv, c.z, acc[10]); acc[11] = fmaf(wv, c.w, acc[11]);
        acc[12] = fmaf(wv, e.x, acc[12]); acc[13] = fmaf(wv, e.y, acc[13]);
        acc[14] = fmaf(wv, e.z, acc[14]); acc[15] = fmaf(wv, e.w, acc[15]);
    }

    float* out = which ? g_K : g_Q;
#pragma unroll
    for (int r = 0; r < 16; ++r)
        out[(size_t)(n0 + r)*DD + t] = acc[r];
}

// ---------------------------------------------------------------------------
// Kernel 2: E[b,h,q,k] = exp(Q . K) (no max-subtraction; |logit| ~ 25 max).
// Block = (b, h, qtile of 64). Thread t owns k=t, loops q.
// ---------------------------------------------------------------------------
__global__ void score_kernel() {
    int b = blockIdx.x, h = blockIdx.y;
    int qb = blockIdx.z * 64;
    int t = threadIdx.x;                 // k index
    __shared__ float Qs[64][32];
    __shared__ float Ks[256][33];

    for (int i = t; i < 64*32; i += 256) {
        int q = i >> 5, j = i & 31;
        Qs[q][j] = g_Q[(size_t)(b*TQ + qb + q)*DD + h*DK + j];
    }
    for (int i = t; i < 256*32; i += 256) {
        int k = i >> 5, j = i & 31;
        Ks[k][j] = g_K[(size_t)(b*TK + k)*DD + h*DK + j];
    }
    __syncthreads();

    float kr[32];
#pragma unroll
    for (int j = 0; j < 32; ++j) kr[j] = Ks[t][j];

    float* ep = g_E + ((size_t)(b*HH + h)*TQ + qb)*TK + t;
#pragma unroll 4
    for (int q = 0; q < 64; ++q) {
        float s = 0.f;
#pragma unroll
        for (int j = 0; j < 32; ++j) s = fmaf(kr[j], Qs[q][j], s);
        ep[(size_t)q*TK] = __expf(fminf(s, 80.f));
    }
}

// ---------------------------------------------------------------------------
// Kernel 3: num/den = E[b,h] @ [mask*value | mask]. qtile=64 per block,
// grid (NB, HH, 4) = 512 blocks x 4 warps -> ~14 warps/SM.
// Thread (qg=t>>2: 2 q rows, fg=t&3: 9 f cols), 36 accumulators.
// k tiled by 32 through SMEM with float4 fills.
// ---------------------------------------------------------------------------
__global__ void apply_kernel(const float* __restrict__ value,
                             const float* __restrict__ mask) {
    int b = blockIdx.x, h = blockIdx.y;
    int q0 = blockIdx.z * 64;
    int t = threadIdx.x;        // 128 threads
    int qg = t >> 2;            // 0..31 -> q local = qg*2 + qq
    int fg = t & 3;             // f = fg*9 + i

    __shared__ float Es[64][33];     // [q][kk]
    __shared__ float Cs[32][73];     // [kk][c]: c<36 -> mask*value, c>=36 -> mask

    float num[2][9], den[2][9];
#pragma unroll
    for (int qq = 0; qq < 2; ++qq)
#pragma unroll
        for (int i = 0; i < 9; ++i) { num[qq][i] = 0.f; den[qq][i] = 0.f; }

    const float* Ebase = g_E + ((size_t)(b*HH + h)*TQ + q0)*TK;

    for (int kt = 0; kt < TK; kt += 32) {
        __syncthreads();
        // Es fill: 64 rows x 32 cols = 512 float4, 128 threads -> 4 each
#pragma unroll
        for (int r = 0; r < 4; ++r) {
            int i = t + r*128;
            int q = i >> 3;
            int kc = (i & 7) * 4;
            float4 v = *(const float4*)(Ebase + (size_t)q*TK + kt + kc);
            Es[q][kc] = v.x; Es[q][kc+1] = v.y; Es[q][kc+2] = v.z; Es[q][kc+3] = v.w;
        }
        // Cs fill: 32k x 36f mv (288 float4) + m (288 float4)
        for (int i = t; i < 576; i += 128) {
            int half = (i >= 288);
            int j = half ? i - 288 : i;
            int k = j / 9;
            int c4 = (j - k*9) * 4;
            size_t base = (size_t)(b*TK + kt + k)*FF + c4;
            float4 mm = *(const float4*)(mask + base);
            if (!half) {
                float4 vv = *(const float4*)(value + base);
                Cs[k][c4+0] = mm.x*vv.x; Cs[k][c4+1] = mm.y*vv.y;
                Cs[k][c4+2] = mm.z*vv.z; Cs[k][c4+3] = mm.w*vv.w;
            } else {
                Cs[k][36+c4+0] = mm.x; Cs[k][36+c4+1] = mm.y;
                Cs[k][36+c4+2] = mm.z; Cs[k][36+c4+3] = mm.w;
            }
        }
        __syncthreads();

#pragma unroll 8
        for (int kk = 0; kk < 32; ++kk) {
            float e0 = Es[qg*2 + 0][kk];
            float e1 = Es[qg*2 + 1][kk];
#pragma unroll
            for (int i = 0; i < 9; ++i) {
                float mv = Cs[kk][fg*9 + i];
                float mo = Cs[kk][36 + fg*9 + i];
                num[0][i] = fmaf(e0, mv, num[0][i]);
                den[0][i] = fmaf(e0, mo, den[0][i]);
                num[1][i] = fmaf(e1, mv, num[1][i]);
                den[1][i] = fmaf(e1, mo, den[1][i]);
            }
        }
    }

#pragma unroll
    for (int qq = 0; qq < 2; ++qq) {
        int q = q0 + qg*2 + qq;
        float* o = g_HN + (size_t)(b*TQ + q)*FF*HH + h;
#pragma unroll
        for (int i = 0; i < 9; ++i) {
            int f = fg*9 + i;
            o[(size_t)f*HH] = __fdividef(num[qq][i], den[qq][i]);
        }
    }
}

// ---------------------------------------------------------------------------
// Kernel 4: fused epilogue. Block per (b,q), thread per d.
// tanh.approx.f32: 1 MUFU op vs exp+div.
// ---------------------------------------------------------------------------
__device__ __forceinline__ float tanh_approx(float x) {
    float y;
    asm("tanh.approx.f32 %0, %1;" : "=f"(y) : "f"(x));
    return y;
}

__global__ void epilogue_kernel(const float* __restrict__ Wc,
                                const float* __restrict__ bc,
                                const float* __restrict__ Wo1,
                                const float* __restrict__ bo1,
                                const float* __restrict__ Wo2,
                                const float* __restrict__ bo2,
                                float* __restrict__ out) {
    int bq = blockIdx.x;
    int d = threadIdx.x;
    __shared__ float hs[FF*HH];     // 288
    __shared__ float w1[FF*SFD];    // 216
    __shared__ float b1s[SFD], w2[SFD];

    for (int i = d; i < FF*HH; i += 256) hs[i] = g_HN[(size_t)bq*FF*HH + i];
    if (d < FF*SFD) w1[d] = Wo1[d];
    if (d < SFD) { b1s[d] = bo1[d]; w2[d] = Wo2[d]; }
    __syncthreads();

    float wc[HH];
#pragma unroll
    for (int h = 0; h < HH; ++h) wc[h] = Wc[h*DD + d];

    float lat[FF];
    float bcd = bc[d];
#pragma unroll
    for (int f = 0; f < FF; ++f) {
        float a = bcd;
#pragma unroll
        for (int h = 0; h < HH; ++h) a = fmaf(hs[f*HH + h], wc[h], a);
        lat[f] = tanh_approx(a);
    }

    float acc = bo2[d];
#pragma unroll
    for (int s = 0; s < SFD; ++s) {
        float a = b1s[s];
#pragma unroll
        for (int f = 0; f < FF; ++f) a = fmaf(lat[f], w1[f*SFD + s], a);
        acc = fmaf(tanh_approx(a), w2[s], acc);
    }
    out[(size_t)bq*DD + d] = acc;
}

// ---------------------------------------------------------------------------
extern "C" void kernel_launch(void* const* d_in, const int* in_sizes, int n_in,
                              void* d_out, int out_size) {
    const float* query = (const float*)d_in[0];
    const float* key   = (const float*)d_in[1];
    const float* value = (const float*)d_in[2];
    const float* mask  = (const float*)d_in[3];
    const float* Wq    = (const float*)d_in[4];
    const float* Wk    = (const float*)d_in[5];
    const float* Wc    = (const float*)d_in[6];
    const float* bc    = (const float*)d_in[7];
    const float* Wo1   = (const float*)d_in[8];
    const float* bo1   = (const float*)d_in[9];
    const float* Wo2   = (const float*)d_in[10];
    const float* bo2   = (const float*)d_in[11];
    float* out = (float*)d_out;

    proj_kernel<<<dim3(NB*TQ/16, 2), 256>>>(query, key, Wq, Wk);
    score_kernel<<<dim3(NB, HH, 4), 256>>>();
    apply_kernel<<<dim3(NB, HH, 4), 128>>>(value, mask);
    epilogue_kernel<<<NB*TQ, 256>>>(Wc, bc, Wo1, bo1, Wo2, bo2, out);
}

// round 3
// speedup vs baseline: 1.6176x; 1.1884x over previous
#include <cuda_runtime.h>

#define NB 16
#define TQ 256
#define TK 256
#define DD 256
#define FF 36
#define HH 8
#define DK 32
#define SFD 6

// Scratch (allocation-free rule: __device__ globals)
__device__ float g_Q[NB*TQ*DD];        // [b][q][h*DK+j]
__device__ float g_K[NB*TK*DD];        // [b][k][h*DK+j]
__device__ float g_E[NB*HH*TQ*TK];     // [b][h][q][k] = exp(score)
__device__ float g_HN[NB*TQ*FF*HH];    // [b][q][f][h]

// ---------------------------------------------------------------------------
// Packed fp32x2 helpers (sm_103a: FFMA2 via PTX only)
// ---------------------------------------------------------------------------
__device__ __forceinline__ float2 fma2(float2 a, float2 b, float2 c) {
    float2 d;
    asm("fma.rn.f32x2 %0, %1, %2, %3;"
        : "=l"(reinterpret_cast<unsigned long long&>(d))
        : "l"(reinterpret_cast<unsigned long long&>(a)),
          "l"(reinterpret_cast<unsigned long long&>(b)),
          "l"(reinterpret_cast<unsigned long long&>(c)));
    return d;
}
__device__ __forceinline__ float2 dup2(float s) { return make_float2(s, s); }
__device__ __forceinline__ float2 tanh2(float2 a) {
    float2 r;
    asm("tanh.approx.f32 %0, %1;" : "=f"(r.x) : "f"(a.x));
    asm("tanh.approx.f32 %0, %1;" : "=f"(r.y) : "f"(a.y));
    return r;
}

// ---------------------------------------------------------------------------
// Kernel 1: head projections, 16 rows/block, row-pairs packed into FFMA2.
// grid (NB*TQ/16, 2): y=0 -> query->g_Q, y=1 -> key->g_K. Thread t = h*32+j.
// ---------------------------------------------------------------------------
__global__ void __launch_bounds__(256) proj_kernel(
        const float* __restrict__ query, const float* __restrict__ key,
        const float* __restrict__ Wq,    const float* __restrict__ Wk) {
    __shared__ float xst[DD][20];        // transposed; 20 -> 16B-aligned rows
    int n0 = blockIdx.x * 16;
    int which = blockIdx.y;
    const float* x = which ? key : query;
    const float* W = which ? Wk : Wq;
    int t = threadIdx.x;

#pragma unroll
    for (int r = 0; r < 16; ++r)
        xst[t][r] = x[(size_t)(n0 + r)*DD + t];
    __syncthreads();

    int h = t >> 5, j = t & 31;
    const float* w = W + h*DD*DK + j;

    float2 acc[8];
#pragma unroll
    for (int r = 0; r < 8; ++r) acc[r] = make_float2(0.f, 0.f);

#pragma unroll 8
    for (int d = 0; d < DD; ++d) {
        float2 wv = dup2(w[d*DK]);
        const float4* xr = (const float4*)&xst[d][0];
        float4 a = xr[0], b = xr[1], c = xr[2], e = xr[3];
        const float2* pa = (const float2*)&a;
        const float2* pb = (const float2*)&b;
        const float2* pc = (const float2*)&c;
        const float2* pe = (const float2*)&e;
        acc[0] = fma2(wv, pa[0], acc[0]);
        acc[1] = fma2(wv, pa[1], acc[1]);
        acc[2] = fma2(wv, pb[0], acc[2]);
        acc[3] = fma2(wv, pb[1], acc[3]);
        acc[4] = fma2(wv, pc[0], acc[4]);
        acc[5] = fma2(wv, pc[1], acc[5]);
        acc[6] = fma2(wv, pe[0], acc[6]);
        acc[7] = fma2(wv, pe[1], acc[7]);
    }

    float* out = which ? g_K : g_Q;
#pragma unroll
    for (int r = 0; r < 8; ++r) {
        out[(size_t)(n0 + 2*r    )*DD + t] = acc[r].x;
        out[(size_t)(n0 + 2*r + 1)*DD + t] = acc[r].y;
    }
}

// ---------------------------------------------------------------------------
// Kernel 2: E = exp(Q.K). Thread t owns k=t; q packed in pairs via transposed
// Q tile (LDS.128 = 4 q's) + pre-duplicated K in registers.
// Block = (b, h, qtile of 64).
// ---------------------------------------------------------------------------
__global__ void __launch_bounds__(256, 2) score_kernel() {
    int b = blockIdx.x, h = blockIdx.y;
    int qb = blockIdx.z * 64;
    int t = threadIdx.x;                 // k index
    __shared__ float Qst[32][68];        // [j][q], 68*4=272 bytes: 16B-aligned rows
    __shared__ float Ks[256][33];

    for (int i = t; i < 64*32; i += 256) {
        int q = i >> 5, j = i & 31;
        Qst[j][q] = g_Q[(size_t)(b*TQ + qb + q)*DD + h*DK + j];
    }
    for (int i = t; i < 256*32; i += 256) {
        int k = i >> 5, j = i & 31;
        Ks[k][j] = g_K[(size_t)(b*TK + k)*DD + h*DK + j];
    }
    __syncthreads();

    float2 kr2[32];
#pragma unroll
    for (int j = 0; j < 32; ++j) kr2[j] = dup2(Ks[t][j]);

    float* ep = g_E + ((size_t)(b*HH + h)*TQ + qb)*TK + t;
#pragma unroll 4
    for (int g = 0; g < 16; ++g) {       // 4 q per group
        float2 a01 = make_float2(0.f, 0.f);
        float2 a23 = make_float2(0.f, 0.f);
#pragma unroll
        for (int j = 0; j < 32; ++j) {
            float4 qv = *(const float4*)&Qst[j][g*4];
            const float2* p = (const float2*)&qv;
            a01 = fma2(p[0], kr2[j], a01);
            a23 = fma2(p[1], kr2[j], a23);
        }
        ep[(size_t)(g*4 + 0)*TK] = __expf(fminf(a01.x, 80.f));
        ep[(size_t)(g*4 + 1)*TK] = __expf(fminf(a01.y, 80.f));
        ep[(size_t)(g*4 + 2)*TK] = __expf(fminf(a23.x, 80.f));
        ep[(size_t)(g*4 + 3)*TK] = __expf(fminf(a23.y, 80.f));
    }
}

// ---------------------------------------------------------------------------
// Kernel 3: num/den = E @ [mask*value | mask], (num,den) packed into FFMA2
// lanes (they share the multiplier e). Cs interleaved: [kk][2f]=m*v, [2f+1]=m.
// Thread (qg: 2 q rows, fg: 9 f's strided by 4). qtile 64 per block.
// ---------------------------------------------------------------------------
__global__ void __launch_bounds__(128) apply_kernel(
        const float* __restrict__ value, const float* __restrict__ mask) {
    int b = blockIdx.x, h = blockIdx.y;
    int q0 = blockIdx.z * 64;
    int t = threadIdx.x;        // 128 threads
    int qg = t >> 2;            // q local = qg*2 + qq
    int fg = t & 3;             // f = fg + 4*i, i=0..8

    __shared__ float Es[64][33];
    __shared__ float Cs[32][74];     // interleaved (mv, m) pairs; 74 -> 8B rows

    float2 nd[2][9];                 // (num, den)
#pragma unroll
    for (int qq = 0; qq < 2; ++qq)
#pragma unroll
        for (int i = 0; i < 9; ++i) nd[qq][i] = make_float2(0.f, 0.f);

    const float* Ebase = g_E + ((size_t)(b*HH + h)*TQ + q0)*TK;

    for (int kt = 0; kt < TK; kt += 32) {
        __syncthreads();
#pragma unroll
        for (int r = 0; r < 4; ++r) {
            int i = t + r*128;
            int q = i >> 3;
            int kc = (i & 7) * 4;
            float4 v = *(const float4*)(Ebase + (size_t)q*TK + kt + kc);
            Es[q][kc] = v.x; Es[q][kc+1] = v.y; Es[q][kc+2] = v.z; Es[q][kc+3] = v.w;
        }
        for (int i = t; i < 288; i += 128) {
            int k = i / 9;
            int c4 = (i - k*9) * 4;
            size_t base = (size_t)(b*TK + kt + k)*FF + c4;
            float4 mm = *(const float4*)(mask + base);
            float4 vv = *(const float4*)(value + base);
            *(float2*)&Cs[k][2*(c4+0)] = make_float2(mm.x*vv.x, mm.x);
            *(float2*)&Cs[k][2*(c4+1)] = make_float2(mm.y*vv.y, mm.y);
            *(float2*)&Cs[k][2*(c4+2)] = make_float2(mm.z*vv.z, mm.z);
            *(float2*)&Cs[k][2*(c4+3)] = make_float2(mm.w*vv.w, mm.w);
        }
        __syncthreads();

#pragma unroll 8
        for (int kk = 0; kk < 32; ++kk) {
            float2 e0 = dup2(Es[qg*2 + 0][kk]);
            float2 e1 = dup2(Es[qg*2 + 1][kk]);
#pragma unroll
            for (int i = 0; i < 9; ++i) {
                float2 c = *(const float2*)&Cs[kk][2*(fg + 4*i)];
                nd[0][i] = fma2(e0, c, nd[0][i]);
                nd[1][i] = fma2(e1, c, nd[1][i]);
            }
        }
    }

#pragma unroll
    for (int qq = 0; qq < 2; ++qq) {
        int q = q0 + qg*2 + qq;
        float* o = g_HN + (size_t)(b*TQ + q)*FF*HH + h;
#pragma unroll
        for (int i = 0; i < 9; ++i) {
            int f = fg + 4*i;
            o[(size_t)f*HH] = __fdividef(nd[qq][i].x, nd[qq][i].y);
        }
    }
}

// ---------------------------------------------------------------------------
// Kernel 4: fused epilogue. Block (128 thr) per (b,q); thread owns d and d+128
// packed into FFMA2 lanes. No lat[] array: per f, tanh then accumulate into
// acc[6]. hs/w1 pre-duplicated in smem so one LDS.64 feeds one FFMA2.
// ---------------------------------------------------------------------------
__global__ void __launch_bounds__(128) epilogue_kernel(
        const float* __restrict__ Wc,  const float* __restrict__ bc,
        const float* __restrict__ Wo1, const float* __restrict__ bo1,
        const float* __restrict__ Wo2, const float* __restrict__ bo2,
        float* __restrict__ out) {
    int bq = blockIdx.x;
    int t  = threadIdx.x;       // d0 = t, d1 = t + 128
    __shared__ float2 hs2[FF*HH];    // duplicated pairs
    __shared__ float2 w12[FF*SFD];

    const float* hn = g_HN + (size_t)bq*FF*HH;
    for (int i = t; i < FF*HH; i += 128) hs2[i] = dup2(hn[i]);
    for (int i = t; i < FF*SFD; i += 128) w12[i] = dup2(Wo1[i]);
    __syncthreads();

    int d0 = t, d1 = t + 128;
    float2 wc2[HH];
#pragma unroll
    for (int h = 0; h < HH; ++h)
        wc2[h] = make_float2(Wc[h*DD + d0], Wc[h*DD + d1]);
    float2 bc2 = make_float2(bc[d0], bc[d1]);

    float2 acc[SFD];
#pragma unroll
    for (int s = 0; s < SFD; ++s) acc[s] = dup2(bo1[s]);

#pragma unroll 4
    for (int f = 0; f < FF; ++f) {
        float2 a = bc2;
#pragma unroll
        for (int h = 0; h < HH; ++h)
            a = fma2(hs2[f*HH + h], wc2[h], a);
        float2 lat = tanh2(a);
#pragma unroll
        for (int s = 0; s < SFD; ++s)
            acc[s] = fma2(lat, w12[f*SFD + s], acc[s]);
    }

    float2 res = make_float2(bo2[d0], bo2[d1]);
#pragma unroll
    for (int s = 0; s < SFD; ++s)
        res = fma2(tanh2(acc[s]), dup2(Wo2[s]), res);

    out[(size_t)bq*DD + d0] = res.x;
    out[(size_t)bq*DD + d1] = res.y;
}

// ---------------------------------------------------------------------------
extern "C" void kernel_launch(void* const* d_in, const int* in_sizes, int n_in,
                              void* d_out, int out_size) {
    const float* query = (const float*)d_in[0];
    const float* key   = (const float*)d_in[1];
    const float* value = (const float*)d_in[2];
    const float* mask  = (const float*)d_in[3];
    const float* Wq    = (const float*)d_in[4];
    const float* Wk    = (const float*)d_in[5];
    const float* Wc    = (const float*)d_in[6];
    const float* bc    = (const float*)d_in[7];
    const float* Wo1   = (const float*)d_in[8];
    const float* bo1   = (const float*)d_in[9];
    const float* Wo2   = (const float*)d_in[10];
    const float* bo2   = (const float*)d_in[11];
    float* out = (float*)d_out;

    proj_kernel<<<dim3(NB*TQ/16, 2), 256>>>(query, key, Wq, Wk);
    score_kernel<<<dim3(NB, HH, 4), 256>>>();
    apply_kernel<<<dim3(NB, HH, 4), 128>>>(value, mask);
    epilogue_kernel<<<NB*TQ, 128>>>(Wc, bc, Wo1, bo1, Wo2, bo2, out);
}